// round 12
// baseline (speedup 1.0000x reference)
#include <cuda_runtime.h>
#include <cuda_fp16.h>
#include <cstdint>

// EdgeBlock: out = relu(concat(cell[src],cell[dst],edge) @ W1 + b1) @ W2 + b2
// v7: fp16 mma.m16n8k16, warp tile 64x64 (1.0 LDS-wf/mma), TILE_M=128,
//     4 warps/CTA, 2 CTAs/SM, XOR-swizzled smem, cp.async W staging,
//     MLP-8 batched gather.

#define THREADS 128
#define TILE_M  128
#define A_BYTES 32768                   // 128 x 128 fp16, swizzled (256B rows)
#define W_BYTES 32768                   // 128 x 128 fp16, swizzled
#define SMEM_BYTES (A_BYTES + W_BYTES)  // 65536 -> 2 CTAs/SM

// pre-transposed fp16 weights, n-major: W1T[n][k]
__device__ __half g_W1T[128 * 384];
__device__ __half g_W2T[128 * 128];

// swizzled byte offset in a [rows x 128 fp16] tile (256B rows, 16B chunks)
#define SWA(row, colh) \
    ((uint32_t)(row) * 256u + (((((uint32_t)(colh)) >> 3) ^ ((uint32_t)(row) & 7u)) << 4) \
     + (((uint32_t)(colh) & 7u) << 1))

// ---------------- helpers ----------------
__device__ __forceinline__ uint32_t smem_u32(const void* p) {
    uint32_t a;
    asm("{ .reg .u64 t; cvta.to.shared.u64 t, %1; cvt.u32.u64 %0, t; }" : "=r"(a) : "l"(p));
    return a;
}
__device__ __forceinline__ void ldm_x4(uint32_t* r, uint32_t addr) {
    asm volatile("ldmatrix.sync.aligned.m8n8.x4.shared.b16 {%0,%1,%2,%3}, [%4];"
                 : "=r"(r[0]), "=r"(r[1]), "=r"(r[2]), "=r"(r[3]) : "r"(addr));
}
__device__ __forceinline__ void mma_f16(float* d, const uint32_t* a, const uint32_t* b) {
    asm volatile(
        "mma.sync.aligned.m16n8k16.row.col.f32.f16.f16.f32 "
        "{%0,%1,%2,%3}, {%4,%5,%6,%7}, {%8,%9}, {%0,%1,%2,%3};"
        : "+f"(d[0]), "+f"(d[1]), "+f"(d[2]), "+f"(d[3])
        : "r"(a[0]), "r"(a[1]), "r"(a[2]), "r"(a[3]), "r"(b[0]), "r"(b[1]));
}
__device__ __forceinline__ void cp16(uint32_t dst, const void* src) {
    asm volatile("cp.async.cg.shared.global [%0], [%1], 16;" :: "r"(dst), "l"(src));
}
#define CP_COMMIT() asm volatile("cp.async.commit_group;" ::: "memory")
#define CP_WAIT0()  asm volatile("cp.async.wait_group 0;" ::: "memory")

// one warp's 64x64 share of a 128(M) x 128(N) x 128(K) fp16 chunk, 8 k16-steps
__device__ __forceinline__ void gemm_chunk(uint32_t At, uint32_t Wt,
                                           float acc[4][8][4],
                                           int wm, int wn, int lane)
{
    const int sub = lane >> 3, l7 = lane & 7;
    const int arow = wm * 64 + (sub & 1) * 8 + l7;     // + t*16
    const int akol = (sub >> 1) * 8;                   // + kk*16
    const int brow = wn * 64 + (sub >> 1) * 8 + l7;    // + p*16
    const int bkol = (sub & 1) * 8;                    // + kk*16
#pragma unroll 1
    for (int kk = 0; kk < 8; ++kk) {
        uint32_t a[4][4];
#pragma unroll
        for (int t = 0; t < 4; ++t)
            ldm_x4(a[t], At + SWA(arow + t * 16, kk * 16 + akol));
        uint32_t b[4][4];
#pragma unroll
        for (int p = 0; p < 4; ++p)
            ldm_x4(b[p], Wt + SWA(brow + p * 16, kk * 16 + bkol));
#pragma unroll
        for (int t = 0; t < 4; ++t)
#pragma unroll
            for (int p = 0; p < 4; ++p) {
                mma_f16(acc[t][2 * p],     a[t], &b[p][0]);
                mma_f16(acc[t][2 * p + 1], a[t], &b[p][2]);
            }
    }
}

// stage one 128n x 128k fp16 tile via cp.async into swizzled layout
__device__ __forceinline__ void stage_w(uint32_t Wt, const __half* src,
                                        int src_stride, int tid)
{
#pragma unroll
    for (int i = 0; i < 16; ++i) {
        int idx = i * 128 + tid;          // 2048 16B-groups
        int row = idx >> 4, c8 = idx & 15;
        cp16(Wt + SWA(row, c8 * 8), src + row * src_stride + c8 * 8);
    }
}

// ---------------- weight prep: transpose to n-major + fp16 ----------------
__global__ void prep_kernel(const float* __restrict__ W1, const float* __restrict__ W2) {
    int i = blockIdx.x * blockDim.x + threadIdx.x;
    if (i < 384 * 128) {
        int k = i >> 7, n = i & 127;
        g_W1T[n * 384 + k] = __float2half_rn(W1[i]);
    }
    if (i < 128 * 128) {
        int k = i >> 7, n = i & 127;
        g_W2T[n * 128 + k] = __float2half_rn(W2[i]);
    }
}

// ---------------- main fused kernel ----------------
__global__ void __launch_bounds__(THREADS, 2)
edgeblock_mma(const float* __restrict__ cell,
              const float* __restrict__ edge,
              const float* __restrict__ b1,
              const float* __restrict__ b2,
              const int*   __restrict__ eidx,
              float* __restrict__ out,
              int E)
{
    extern __shared__ __align__(16) char sm[];
    char* At = sm;
    const uint32_t sb   = smem_u32(sm);
    const uint32_t At_u = sb;
    const uint32_t Wt_u = sb + A_BYTES;

    const int tid = threadIdx.x, wid = tid >> 5, lane = tid & 31;
    const int wm = wid & 1, wn = wid >> 1;      // 2m x 2n grid, 64x64 warp tiles
    const int e0 = blockIdx.x * TILE_M;

    const int g_row  = tid >> 2;      // 0..31 (+ 32*b)
    const int g_c4b  = (tid & 3) * 8; // float4 col base (+ i, i=0..7)

    float acc[4][8][4];
#pragma unroll
    for (int t = 0; t < 4; ++t)
#pragma unroll
        for (int j = 0; j < 8; ++j)
#pragma unroll
            for (int c = 0; c < 4; ++c) acc[t][j][c] = 0.0f;

    // ===== GEMM1: 3 K-chunks of 128 =====
#pragma unroll 1
    for (int ch = 0; ch < 3; ++ch) {
        stage_w(Wt_u, g_W1T + ch * 128, 384, tid);   // async W chunk
        CP_COMMIT();

        // gather 128 rows x 128 f32 -> fp16: 4 batches, MLP 8
#pragma unroll 1
        for (int b = 0; b < 4; ++b) {
            int row = b * 32 + g_row;
            int e = e0 + row; int eL = (e < E) ? e : (E - 1);
            const float* base;
            if (ch == 0)      base = cell + (size_t)__ldg(&eidx[eL]) * 128;
            else if (ch == 1) base = cell + (size_t)__ldg(&eidx[E + eL]) * 128;
            else              base = edge + (size_t)eL * 128;
            float4 v[8];
#pragma unroll
            for (int i = 0; i < 8; ++i)
                v[i] = reinterpret_cast<const float4*>(base)[g_c4b + i];
#pragma unroll
            for (int i = 0; i < 8; ++i) {
                int c4 = g_c4b + i;
                __half2 h0 = __float22half2_rn(make_float2(v[i].x, v[i].y));
                __half2 h1 = __float22half2_rn(make_float2(v[i].z, v[i].w));
                uint64_t q = ((uint64_t)*reinterpret_cast<uint32_t*>(&h1) << 32) |
                              *reinterpret_cast<uint32_t*>(&h0);
                *reinterpret_cast<uint64_t*>(At + SWA(row, c4 * 4)) = q;
            }
        }

        CP_WAIT0();
        __syncthreads();
        gemm_chunk(At_u, Wt_u, acc, wm, wn, lane);
        __syncthreads();
    }

    // ===== epilogue1: h = relu(acc+b1) -> fp16 -> A tile; prefetch W2 =====
    stage_w(Wt_u, g_W2T, 128, tid);
    CP_COMMIT();
    {
        const int colb = wn * 64 + (lane & 3) * 2;
        const int rowb = wm * 64 + (lane >> 2);
#pragma unroll
        for (int t = 0; t < 4; ++t)
#pragma unroll
            for (int j = 0; j < 8; ++j) {
                int col = colb + j * 8;
                float bx = __ldg(&b1[col]), by = __ldg(&b1[col + 1]);
#pragma unroll
                for (int half = 0; half < 2; ++half) {
                    int row = rowb + t * 16 + half * 8;
                    __half2 h2 = __float22half2_rn(make_float2(
                        fmaxf(acc[t][j][2 * half]     + bx, 0.0f),
                        fmaxf(acc[t][j][2 * half + 1] + by, 0.0f)));
                    *reinterpret_cast<uint32_t*>(At + SWA(row, col)) =
                        *reinterpret_cast<uint32_t*>(&h2);
                }
            }
#pragma unroll
        for (int t = 0; t < 4; ++t)
#pragma unroll
            for (int j = 0; j < 8; ++j)
#pragma unroll
                for (int c = 0; c < 4; ++c) acc[t][j][c] = 0.0f;
    }
    CP_WAIT0();
    __syncthreads();

    // ===== GEMM2: [128 x 128] @ W2 =====
    gemm_chunk(At_u, Wt_u, acc, wm, wn, lane);

    // ===== epilogue2: + b2, store =====
    {
        const int colb = wn * 64 + (lane & 3) * 2;
        const int rowb = wm * 64 + (lane >> 2);
#pragma unroll
        for (int t = 0; t < 4; ++t)
#pragma unroll
            for (int j = 0; j < 8; ++j) {
                int col = colb + j * 8;
                float bx = __ldg(&b2[col]), by = __ldg(&b2[col + 1]);
#pragma unroll
                for (int half = 0; half < 2; ++half) {
                    int row = rowb + t * 16 + half * 8;
                    int e = e0 + row;
                    if (e < E) {
                        float2 o = make_float2(acc[t][j][2 * half] + bx,
                                               acc[t][j][2 * half + 1] + by);
                        *reinterpret_cast<float2*>(out + (size_t)e * 128 + col) = o;
                    }
                }
            }
    }
}

extern "C" void kernel_launch(void* const* d_in, const int* in_sizes, int n_in,
                              void* d_out, int out_size) {
    const float* cell = (const float*)d_in[0];   // [50000,128]
    const float* edge = (const float*)d_in[1];   // [E,128]
    const float* W1   = (const float*)d_in[2];   // [384,128]
    const float* b1   = (const float*)d_in[3];   // [128]
    const float* W2   = (const float*)d_in[4];   // [128,128]
    const float* b2   = (const float*)d_in[5];   // [128]
    const int*   eidx = (const int*)d_in[6];     // [2,E]
    float* out = (float*)d_out;

    int E = in_sizes[6] / 2;

    prep_kernel<<<(384 * 128 + 255) / 256, 256>>>(W1, W2);

    cudaFuncSetAttribute(edgeblock_mma,
                         cudaFuncAttributeMaxDynamicSharedMemorySize, SMEM_BYTES);
    int grid = (E + TILE_M - 1) / TILE_M;
    edgeblock_mma<<<grid, THREADS, SMEM_BYTES>>>(cell, edge, b1, b2, eidx, out, E);
}

// round 13
// speedup vs baseline: 1.4973x; 1.4973x over previous
#include <cuda_runtime.h>
#include <cuda_fp16.h>
#include <cstdint>

// EdgeBlock: out = relu(concat(cell[src],cell[dst],edge) @ W1 + b1) @ W2 + b2
// v8 = v6 (fp16 m16n8k16, warp tile 32x64, 48 KB swizzled smem) + register
//      diet (gather batch 4) + __launch_bounds__(128,4) -> 4 CTAs/SM.

#define THREADS 128
#define TILE_M  64
#define A_BYTES 16384                   // 64 x 128 fp16, swizzled (256B rows)
#define W_BYTES 32768                   // 128 x 128 fp16, swizzled
#define SMEM_BYTES (A_BYTES + W_BYTES)  // 49152 -> 4 CTAs/SM (smem), regs<=128

// pre-transposed fp16 weights, n-major: W1T[n][k]
__device__ __half g_W1T[128 * 384];
__device__ __half g_W2T[128 * 128];

// swizzled byte offset in a [rows x 128 fp16] tile (256B rows, 16B chunks)
#define SWA(row, colh) \
    ((uint32_t)(row) * 256u + (((((uint32_t)(colh)) >> 3) ^ ((uint32_t)(row) & 7u)) << 4) \
     + (((uint32_t)(colh) & 7u) << 1))

// ---------------- helpers ----------------
__device__ __forceinline__ uint32_t smem_u32(const void* p) {
    uint32_t a;
    asm("{ .reg .u64 t; cvta.to.shared.u64 t, %1; cvt.u32.u64 %0, t; }" : "=r"(a) : "l"(p));
    return a;
}
__device__ __forceinline__ void ldm_x4(uint32_t* r, uint32_t addr) {
    asm volatile("ldmatrix.sync.aligned.m8n8.x4.shared.b16 {%0,%1,%2,%3}, [%4];"
                 : "=r"(r[0]), "=r"(r[1]), "=r"(r[2]), "=r"(r[3]) : "r"(addr));
}
__device__ __forceinline__ void mma_f16(float* d, const uint32_t* a, const uint32_t* b) {
    asm volatile(
        "mma.sync.aligned.m16n8k16.row.col.f32.f16.f16.f32 "
        "{%0,%1,%2,%3}, {%4,%5,%6,%7}, {%8,%9}, {%0,%1,%2,%3};"
        : "+f"(d[0]), "+f"(d[1]), "+f"(d[2]), "+f"(d[3])
        : "r"(a[0]), "r"(a[1]), "r"(a[2]), "r"(a[3]), "r"(b[0]), "r"(b[1]));
}
__device__ __forceinline__ void cp16(uint32_t dst, const void* src) {
    asm volatile("cp.async.cg.shared.global [%0], [%1], 16;" :: "r"(dst), "l"(src));
}
#define CP_COMMIT() asm volatile("cp.async.commit_group;" ::: "memory")
#define CP_WAIT0()  asm volatile("cp.async.wait_group 0;" ::: "memory")

// one warp's 32x64 share of a 64(M) x 128(N) x 128(K) fp16 chunk, 8 k16-steps
__device__ __forceinline__ void gemm_chunk(uint32_t At, uint32_t Wt,
                                           float acc[2][8][4],
                                           int wm, int wn, int lane)
{
    const int sub = lane >> 3, l7 = lane & 7;
    const int arow = wm * 32 + (sub & 1) * 8 + l7;     // + t*16
    const int akol = (sub >> 1) * 8;                   // + kk*16
    const int brow = wn * 64 + (sub >> 1) * 8 + l7;    // + p*16
    const int bkol = (sub & 1) * 8;                    // + kk*16
#pragma unroll 2
    for (int kk = 0; kk < 8; ++kk) {
        uint32_t a[2][4];
#pragma unroll
        for (int t = 0; t < 2; ++t)
            ldm_x4(a[t], At + SWA(arow + t * 16, kk * 16 + akol));
        uint32_t b[4][4];
#pragma unroll
        for (int p = 0; p < 4; ++p)
            ldm_x4(b[p], Wt + SWA(brow + p * 16, kk * 16 + bkol));
#pragma unroll
        for (int t = 0; t < 2; ++t)
#pragma unroll
            for (int p = 0; p < 4; ++p) {
                mma_f16(acc[t][2 * p],     a[t], &b[p][0]);
                mma_f16(acc[t][2 * p + 1], a[t], &b[p][2]);
            }
    }
}

// stage one 128n x 128k fp16 tile via cp.async into swizzled layout
__device__ __forceinline__ void stage_w(uint32_t Wt, const __half* src,
                                        int src_stride, int tid)
{
#pragma unroll
    for (int i = 0; i < 16; ++i) {
        int idx = i * 128 + tid;          // 2048 16B-groups
        int row = idx >> 4, c8 = idx & 15;
        cp16(Wt + SWA(row, c8 * 8), src + row * src_stride + c8 * 8);
    }
}

// ---------------- weight prep: transpose to n-major + fp16 ----------------
__global__ void prep_kernel(const float* __restrict__ W1, const float* __restrict__ W2) {
    int i = blockIdx.x * blockDim.x + threadIdx.x;
    if (i < 384 * 128) {
        int k = i >> 7, n = i & 127;
        g_W1T[n * 384 + k] = __float2half_rn(W1[i]);
    }
    if (i < 128 * 128) {
        int k = i >> 7, n = i & 127;
        g_W2T[n * 128 + k] = __float2half_rn(W2[i]);
    }
}

// ---------------- main fused kernel ----------------
__global__ void __launch_bounds__(THREADS, 4)
edgeblock_mma(const float* __restrict__ cell,
              const float* __restrict__ edge,
              const float* __restrict__ b1,
              const float* __restrict__ b2,
              const int*   __restrict__ eidx,
              float* __restrict__ out,
              int E)
{
    extern __shared__ __align__(16) char sm[];
    char* At = sm;
    const uint32_t sb   = smem_u32(sm);
    const uint32_t At_u = sb;
    const uint32_t Wt_u = sb + A_BYTES;

    const int tid = threadIdx.x, wid = tid >> 5, lane = tid & 31;
    const int wm = wid & 1, wn = wid >> 1;      // 2m x 2n grid, 32x64 warp tiles
    const int e0 = blockIdx.x * TILE_M;

    const int g_rsub = wid * 4 + (lane >> 3);   // row within 16-row group
    const int g_l7   = lane & 7;

    float acc[2][8][4];
#pragma unroll
    for (int t = 0; t < 2; ++t)
#pragma unroll
        for (int j = 0; j < 8; ++j)
#pragma unroll
            for (int c = 0; c < 4; ++c) acc[t][j][c] = 0.0f;

    // ===== GEMM1: 3 K-chunks of 128 =====
#pragma unroll 1
    for (int ch = 0; ch < 3; ++ch) {
        stage_w(Wt_u, g_W1T + ch * 128, 384, tid);   // async W chunk
        CP_COMMIT();

        // gather 64 rows x 128 f32 -> fp16: 4 batches of 16 rows, MLP 4
#pragma unroll 1
        for (int b = 0; b < 4; ++b) {
            int row = b * 16 + g_rsub;
            int e = e0 + row; int eL = (e < E) ? e : (E - 1);
            const float* base;
            if (ch == 0)      base = cell + (size_t)__ldg(&eidx[eL]) * 128;
            else if (ch == 1) base = cell + (size_t)__ldg(&eidx[E + eL]) * 128;
            else              base = edge + (size_t)eL * 128;
            float4 v[4];
#pragma unroll
            for (int i = 0; i < 4; ++i)
                v[i] = reinterpret_cast<const float4*>(base)[g_l7 + 8 * i];
#pragma unroll
            for (int i = 0; i < 4; ++i) {
                int c4 = g_l7 + 8 * i;
                __half2 h0 = __float22half2_rn(make_float2(v[i].x, v[i].y));
                __half2 h1 = __float22half2_rn(make_float2(v[i].z, v[i].w));
                uint64_t q = ((uint64_t)*reinterpret_cast<uint32_t*>(&h1) << 32) |
                              *reinterpret_cast<uint32_t*>(&h0);
                *reinterpret_cast<uint64_t*>(At + SWA(row, c4 * 4)) = q;
            }
        }

        CP_WAIT0();
        __syncthreads();
        gemm_chunk(At_u, Wt_u, acc, wm, wn, lane);
        __syncthreads();
    }

    // ===== epilogue1: h = relu(acc+b1) -> fp16 -> A tile; prefetch W2 =====
    stage_w(Wt_u, g_W2T, 128, tid);
    CP_COMMIT();
    {
        const int colb = wn * 64 + (lane & 3) * 2;
        const int rowb = wm * 32 + (lane >> 2);
#pragma unroll
        for (int t = 0; t < 2; ++t)
#pragma unroll
            for (int j = 0; j < 8; ++j) {
                int col = colb + j * 8;
                float bx = __ldg(&b1[col]), by = __ldg(&b1[col + 1]);
#pragma unroll
                for (int half = 0; half < 2; ++half) {
                    int row = rowb + t * 16 + half * 8;
                    __half2 h2 = __float22half2_rn(make_float2(
                        fmaxf(acc[t][j][2 * half]     + bx, 0.0f),
                        fmaxf(acc[t][j][2 * half + 1] + by, 0.0f)));
                    *reinterpret_cast<uint32_t*>(At + SWA(row, col)) =
                        *reinterpret_cast<uint32_t*>(&h2);
                }
            }
#pragma unroll
        for (int t = 0; t < 2; ++t)
#pragma unroll
            for (int j = 0; j < 8; ++j)
#pragma unroll
                for (int c = 0; c < 4; ++c) acc[t][j][c] = 0.0f;
    }
    CP_WAIT0();
    __syncthreads();

    // ===== GEMM2: [64 x 128] @ W2 =====
    gemm_chunk(At_u, Wt_u, acc, wm, wn, lane);

    // ===== epilogue2: + b2, store =====
    {
        const int colb = wn * 64 + (lane & 3) * 2;
        const int rowb = wm * 32 + (lane >> 2);
#pragma unroll
        for (int t = 0; t < 2; ++t)
#pragma unroll
            for (int j = 0; j < 8; ++j) {
                int col = colb + j * 8;
                float bx = __ldg(&b2[col]), by = __ldg(&b2[col + 1]);
#pragma unroll
                for (int half = 0; half < 2; ++half) {
                    int row = rowb + t * 16 + half * 8;
                    int e = e0 + row;
                    if (e < E) {
                        float2 o = make_float2(acc[t][j][2 * half] + bx,
                                               acc[t][j][2 * half + 1] + by);
                        *reinterpret_cast<float2*>(out + (size_t)e * 128 + col) = o;
                    }
                }
            }
    }
}

extern "C" void kernel_launch(void* const* d_in, const int* in_sizes, int n_in,
                              void* d_out, int out_size) {
    const float* cell = (const float*)d_in[0];   // [50000,128]
    const float* edge = (const float*)d_in[1];   // [E,128]
    const float* W1   = (const float*)d_in[2];   // [384,128]
    const float* b1   = (const float*)d_in[3];   // [128]
    const float* W2   = (const float*)d_in[4];   // [128,128]
    const float* b2   = (const float*)d_in[5];   // [128]
    const int*   eidx = (const int*)d_in[6];     // [2,E]
    float* out = (float*)d_out;

    int E = in_sizes[6] / 2;

    prep_kernel<<<(384 * 128 + 255) / 256, 256>>>(W1, W2);

    cudaFuncSetAttribute(edgeblock_mma,
                         cudaFuncAttributeMaxDynamicSharedMemorySize, SMEM_BYTES);
    int grid = (E + TILE_M - 1) / TILE_M;
    edgeblock_mma<<<grid, THREADS, SMEM_BYTES>>>(cell, edge, b1, b2, eidx, out, E);
}